// round 13
// baseline (speedup 1.0000x reference)
#include <cuda_runtime.h>
#include <cuda_fp16.h>
#include <cstdint>

// ============================================================================
// QuadraticConv2D via fp16 HMMA GEMM, register-carried pipeline,
// 2 pairs per barrier phase (27 phases instead of 54):
//   phase q (chunk = pairs 2q+1, 2q+2):
//     wait B(chunk q) -> barrier -> cp.async B(chunk q+1)
//     LDG A(next pair a) -> MMA(pair a) -> STS A(a)
//     LDG A(next pair b) -> MMA(pair b) -> STS A(b)
//   double-buffered 2-pair SMEM chunks; p=0 folded into fp32 bias.
// out[m,o] = bias[o] + sum_{p=(i,j)>0} sum_c S_i[m,c]*S_j[m,c]*W[p,c,o]
// ============================================================================

#define HW     56
#define CH     64
#define OD     128
#define NPOS   (8 * 56 * 56)      // 25088
#define MT     64                 // M rows per CTA
#define NTILES (NPOS / MT)        // 392
#define BDIM   256
#define NPAIRS 55
#define NCHUNK 27                 // pairs 1..54, two per chunk

#define ASTR   144                // A row stride bytes
#define BSTR   272                // B row stride bytes

// SMEM layout (bytes): 2 chunks, each = 2 A tiles + 2 B tiles
#define ABUF_SZ   9216            // 64 x 144
#define BBUF_SZ   17408           // 64 x 272
#define CHUNK_SZ  (2 * ABUF_SZ + 2 * BBUF_SZ)    // 53248
#define A_OFF(b, s) ((b) * CHUNK_SZ + (s) * ABUF_SZ)
#define B_OFF(b, s) ((b) * CHUNK_SZ + 2 * ABUF_SZ + (s) * BBUF_SZ)
#define MB_OFF    (2 * CHUNK_SZ)                 // 106496
#define MK_OFF    (MB_OFF + 256)
#define SMEM_TOTAL (MK_OFF + 256)                // 107008

// pre-converted weights [p][c*136 + o] fp16, and fp32 bias from pair 0
__device__ __align__(16) __half g_Bh[NPAIRS][CH * (BSTR / 2)];
__device__ __align__(16) float  g_bias[OD];

__constant__ unsigned char cII[55] = {
    0,0,0,0,0,0,0,0,0,0, 1,1,1,1,1,1,1,1,1, 2,2,2,2,2,2,2,2,
    3,3,3,3,3,3,3, 4,4,4,4,4,4, 5,5,5,5,5, 6,6,6,6, 7,7,7, 8,8, 9};
__constant__ unsigned char cJJ[55] = {
    0,1,2,3,4,5,6,7,8,9, 1,2,3,4,5,6,7,8,9, 2,3,4,5,6,7,8,9,
    3,4,5,6,7,8,9, 4,5,6,7,8,9, 5,6,7,8,9, 6,7,8,9, 7,8,9, 8,9, 9};

__device__ __forceinline__ uint32_t smem_to_u32(const void* p) {
    uint32_t a;
    asm("{ .reg .u64 t; cvta.to.shared.u64 t, %1; cvt.u32.u64 %0, t; }"
        : "=r"(a) : "l"(p));
    return a;
}

#define LDSM_X4(r, addr) \
    asm volatile("ldmatrix.sync.aligned.m8n8.x4.shared.b16 {%0,%1,%2,%3}, [%4];" \
                 : "=r"((r)[0]), "=r"((r)[1]), "=r"((r)[2]), "=r"((r)[3]) \
                 : "r"(addr))
#define LDSM_X4T(r, addr) \
    asm volatile("ldmatrix.sync.aligned.m8n8.x4.trans.shared.b16 {%0,%1,%2,%3}, [%4];" \
                 : "=r"((r)[0]), "=r"((r)[1]), "=r"((r)[2]), "=r"((r)[3]) \
                 : "r"(addr))
#define CP_ASYNC16(dst, src) \
    asm volatile("cp.async.cg.shared.global [%0], [%1], 16;" \
                 :: "r"(dst), "l"(src) : "memory")
#define CP_COMMIT() asm volatile("cp.async.commit_group;" ::: "memory")
#define CP_WAIT0()  asm volatile("cp.async.wait_group 0;" ::: "memory")

__device__ __forceinline__ void mma_f16(float* c, const uint32_t* a, const uint32_t* b) {
    asm volatile(
        "mma.sync.aligned.m16n8k16.row.col.f32.f16.f16.f32 "
        "{%0,%1,%2,%3}, {%4,%5,%6,%7}, {%8,%9}, {%0,%1,%2,%3};"
        : "+f"(c[0]), "+f"(c[1]), "+f"(c[2]), "+f"(c[3])
        : "r"(a[0]), "r"(a[1]), "r"(a[2]), "r"(a[3]), "r"(b[0]), "r"(b[1]));
}

// ---------------------------------------------------------------------------
// Prep (single kernel): weight convert + pair-0 bias reduction
// ---------------------------------------------------------------------------
__global__ void prep_all(const float* __restrict__ wt) {
    int idx = blockIdx.x * blockDim.x + threadIdx.x;
    if (idx < NPAIRS * CH * OD) {
        int p = idx / (CH * OD);
        int r = idx - p * CH * OD;
        int c = r / OD;
        int o = r - c * OD;
        g_Bh[p][c * (BSTR / 2) + o] = __float2half(wt[(p * CH + c) * OD + o]);
    }
    if (blockIdx.x == 0 && threadIdx.x < OD) {
        int o = threadIdx.x;
        float s = 0.f;
        #pragma unroll
        for (int c = 0; c < CH; c++) s += wt[c * OD + o];   // pair 0 slice
        g_bias[o] = s;
    }
}

// ---------------------------------------------------------------------------
__global__ void __launch_bounds__(BDIM, 2)
qconv_pipe(const float* __restrict__ in, float* __restrict__ out) {
    extern __shared__ unsigned char smem[];
    const uint32_t sb = smem_to_u32(smem);
    int* mbase_s = (int*)(smem + MB_OFF);
    int* mmask_s = (int*)(smem + MK_OFF);

    const int tid  = threadIdx.x;
    const int wid  = tid >> 5;
    const int lane = tid & 31;
    const int gm0  = blockIdx.x * MT;

    if (tid < MT) {
        int gm  = gm0 + tid;
        int b   = gm / (HW * HW);
        int rem = gm - b * HW * HW;
        int h   = rem / HW;
        int w   = rem - h * HW;
        mbase_s[tid] = ((b * HW + (h - 1)) * HW + (w - 1)) * CH;
        int mask = 0;
        #pragma unroll
        for (int kk = 0; kk < 9; kk++) {
            int hh = h + kk / 3 - 1, ww = w + kk % 3 - 1;
            if (hh >= 0 && hh < HW && ww >= 0 && ww < HW) mask |= (1 << kk);
        }
        mmask_s[tid] = mask;
    }
    __syncthreads();

    // A-gen mapping: thread owns row am, 16-channel quarter cq
    const int am   = tid >> 2;
    const int cq   = (tid & 3) * 16;
    const int base = mbase_s[am];
    const int mask = mmask_s[am];

    // GEMM mapping: 8 warps = 2(M) x 4(N); warp tile 32 x 32
    const int m0 = (wid & 1) * 32;
    const int n0 = (wid >> 1) * 32;
    const uint32_t aoff = (uint32_t)((m0 + (lane & 15)) * ASTR + (lane >> 4) * 16);
    const uint32_t boff = (uint32_t)((lane & 15) * BSTR + (n0 + ((lane >> 4) & 1) * 8) * 2);

    float acc[2][4][4];
    #pragma unroll
    for (int mt = 0; mt < 2; mt++)
        #pragma unroll
        for (int nt = 0; nt < 4; nt++)
            #pragma unroll
            for (int q = 0; q < 4; q++) acc[mt][nt][q] = 0.f;

    const float4 ONES = make_float4(1.f, 1.f, 1.f, 1.f);
    const float4 ZERO = make_float4(0.f, 0.f, 0.f, 0.f);

    // ---- helpers ----
    auto issue_loads = [&](int p, float4* si4, float4* sj4) {
        const int i = cII[p], j = cJJ[p];
        const int kj = j - 1, ki = i - 1;
        const int offj = ((kj / 3) * HW + (kj % 3)) * CH;          // j >= 1 here
        const int offi = (i > 0) ? ((ki / 3) * HW + (ki % 3)) * CH : 0;
        const bool vj = (mask >> kj) & 1;
        const bool vi = (i == 0) || ((mask >> ki) & 1);
        #pragma unroll
        for (int g = 0; g < 4; g++) {
            const int c = cq + g * 4;
            sj4[g] = vj ? *(const float4*)(in + base + offj + c) : ZERO;
            si4[g] = (i == 0) ? ONES : (vi ? *(const float4*)(in + base + offi + c) : ZERO);
        }
    };
    auto store_A = [&](int buf, int slot, const float4* si4, const float4* sj4) {
        unsigned char* ah = smem + A_OFF(buf, slot);
        #pragma unroll
        for (int g = 0; g < 4; g++) {
            const int c = cq + g * 4;
            __half2 hA = __floats2half2_rn(si4[g].x * sj4[g].x, si4[g].y * sj4[g].y);
            __half2 hB = __floats2half2_rn(si4[g].z * sj4[g].z, si4[g].w * sj4[g].w);
            *(uint2*)(ah + am * ASTR + c * 2) =
                make_uint2(*(unsigned*)&hA, *(unsigned*)&hB);
        }
    };
    auto stage_B = [&](int p, int buf, int slot) {
        const char* shp = (const char*)g_Bh[p];
        const uint32_t dh = sb + B_OFF(buf, slot);
        #pragma unroll
        for (int t = 0; t < 5; t++) {
            int x = tid + t * BDIM;              // 1088 16B chunks
            if (x < BBUF_SZ / 16) CP_ASYNC16(dh + x * 16, shp + x * 16);
        }
    };
    auto mma_pair = [&](int buf, int slot) {
        const uint32_t abase = sb + A_OFF(buf, slot) + aoff;
        const uint32_t bbase = sb + B_OFF(buf, slot) + boff;
        #pragma unroll
        for (int kk = 0; kk < 4; kk++) {
            uint32_t a0[4], a1[4];
            LDSM_X4(a0, abase + kk * 32);
            LDSM_X4(a1, abase + kk * 32 + 16 * ASTR);
            const uint32_t bb = bbase + kk * 16 * BSTR;
            #pragma unroll
            for (int t = 0; t < 4; t += 2) {
                uint32_t bh[4];
                LDSM_X4T(bh, bb + t * 16);
                mma_f16(acc[0][t],     a0, bh);
                mma_f16(acc[0][t + 1], a0, bh + 2);
                mma_f16(acc[1][t],     a1, bh);
                mma_f16(acc[1][t + 1], a1, bh + 2);
            }
        }
    };

    // ---- prologue: chunk 0 = pairs 1,2 ----
    stage_B(1, 0, 0);
    stage_B(2, 0, 1);
    CP_COMMIT();
    {
        float4 si4[4], sj4[4];
        issue_loads(1, si4, sj4); store_A(0, 0, si4, sj4);
        issue_loads(2, si4, sj4); store_A(0, 1, si4, sj4);
    }

    // ---- main loop: 27 chunks, one barrier each ----
    int buf = 0;
    for (int q = 0; q < NCHUNK; q++) {
        const int p0   = 2 * q + 1;              // pairs p0, p0+1 in this chunk
        const bool more = (q + 1 < NCHUNK);

        CP_WAIT0();                              // B(chunk q) landed
        __syncthreads();                         // chunk q visible; buf^1 free

        if (more) {
            stage_B(p0 + 2, buf ^ 1, 0);
            stage_B(p0 + 3, buf ^ 1, 1);
        }
        CP_COMMIT();                             // unconditional: group invariant

        float4 si4[4], sj4[4];
        if (more) issue_loads(p0 + 2, si4, sj4); // LDGs fly across MMA block
        mma_pair(buf, 0);                        // 32 HMMA
        if (more) {
            store_A(buf ^ 1, 0, si4, sj4);
            issue_loads(p0 + 3, si4, sj4);
        }
        mma_pair(buf, 1);                        // 32 HMMA
        if (more) store_A(buf ^ 1, 1, si4, sj4);

        buf ^= 1;
    }

    // ---- epilogue: add fp32 bias (pair 0) and store ----
    float* op = out + (size_t)gm0 * OD;
    const int rr = lane >> 2;
    const int cc = (lane & 3) * 2;
    #pragma unroll
    for (int mt = 0; mt < 2; mt++) {
        #pragma unroll
        for (int nt = 0; nt < 4; nt++) {
            const int r0 = m0 + mt * 16 + rr;
            const int cn = n0 + nt * 8 + cc;
            const float b0 = g_bias[cn], b1 = g_bias[cn + 1];
            *(float2*)(op + (size_t)r0 * OD + cn) =
                make_float2(acc[mt][nt][0] + b0, acc[mt][nt][1] + b1);
            *(float2*)(op + (size_t)(r0 + 8) * OD + cn) =
                make_float2(acc[mt][nt][2] + b0, acc[mt][nt][3] + b1);
        }
    }
}

// ---------------------------------------------------------------------------
extern "C" void kernel_launch(void* const* d_in, const int* in_sizes, int n_in,
                              void* d_out, int out_size) {
    const float* in = (const float*)d_in[0];
    const float* wt = (const float*)d_in[1];
    if (n_in >= 2 && in_sizes[0] == NPAIRS * CH * OD) {
        const float* t = in; in = wt; wt = t;
    }
    float* out = (float*)d_out;

    prep_all<<<(NPAIRS * CH * OD + 255) / 256, 256>>>(wt);

    cudaFuncSetAttribute(qconv_pipe,
                         cudaFuncAttributeMaxDynamicSharedMemorySize, SMEM_TOTAL);
    qconv_pipe<<<NTILES, BDIM, SMEM_TOTAL>>>(in, out);
}

// round 14
// speedup vs baseline: 1.1643x; 1.1643x over previous
#include <cuda_runtime.h>
#include <cuda_fp16.h>
#include <cstdint>

// ============================================================================
// QuadraticConv2D via fp16 HMMA GEMM, register-carried pipeline (depth 3).
//   (round-12 structure, reverted from the 2-pair-chunk experiment)
//   - 2M x 4N warp grid, triple-buffered SMEM, wait_group 1 (2 B copies in flight)
//   - p=0 (ones*ones) folded into an fp32 bias vector added in the epilogue
//   - every warp: LDG A(p+2) -> wait B(p) -> cp.async B(p+2) -> MMA(p)
//                 -> cvt+STS A(p+2); one __syncthreads per pair
//   - single merged, vectorized prep kernel (weights fp16 + fp32 bias)
// out[m,o] = bias[o] + sum_{p=(i,j)>0} sum_c S_i[m,c]*S_j[m,c]*W[p,c,o]
// ============================================================================

#define HW     56
#define CH     64
#define OD     128
#define NPOS   (8 * 56 * 56)      // 25088
#define MT     64                 // M rows per CTA
#define NTILES (NPOS / MT)        // 392
#define BDIM   256
#define NPAIRS 55
#define NGEMM  54                 // pairs 1..54 go through the GEMM

#define ASTR   144                // A row stride bytes
#define BSTR   272                // B row stride bytes

// SMEM layout (bytes), triple buffered
#define ABUF_SZ   9216            // 64 x 144
#define A_OFF(b)  ((b) * ABUF_SZ)                 // b in 0..2
#define BBUF_SZ   17408           // 64 x 272
#define B_OFF(b)  (27648 + (b) * BBUF_SZ)
#define MB_OFF    79872
#define MK_OFF    80128
#define SMEM_TOTAL 80384

// pre-converted weights [p][c*136 + o] fp16, and fp32 bias from pair 0
__device__ __align__(16) __half g_Bh[NPAIRS][CH * (BSTR / 2)];
__device__ __align__(16) float  g_bias[OD];

__constant__ unsigned char cII[55] = {
    0,0,0,0,0,0,0,0,0,0, 1,1,1,1,1,1,1,1,1, 2,2,2,2,2,2,2,2,
    3,3,3,3,3,3,3, 4,4,4,4,4,4, 5,5,5,5,5, 6,6,6,6, 7,7,7, 8,8, 9};
__constant__ unsigned char cJJ[55] = {
    0,1,2,3,4,5,6,7,8,9, 1,2,3,4,5,6,7,8,9, 2,3,4,5,6,7,8,9,
    3,4,5,6,7,8,9, 4,5,6,7,8,9, 5,6,7,8,9, 6,7,8,9, 7,8,9, 8,9, 9};

__device__ __forceinline__ uint32_t smem_to_u32(const void* p) {
    uint32_t a;
    asm("{ .reg .u64 t; cvta.to.shared.u64 t, %1; cvt.u32.u64 %0, t; }"
        : "=r"(a) : "l"(p));
    return a;
}

#define LDSM_X4(r, addr) \
    asm volatile("ldmatrix.sync.aligned.m8n8.x4.shared.b16 {%0,%1,%2,%3}, [%4];" \
                 : "=r"((r)[0]), "=r"((r)[1]), "=r"((r)[2]), "=r"((r)[3]) \
                 : "r"(addr))
#define LDSM_X4T(r, addr) \
    asm volatile("ldmatrix.sync.aligned.m8n8.x4.trans.shared.b16 {%0,%1,%2,%3}, [%4];" \
                 : "=r"((r)[0]), "=r"((r)[1]), "=r"((r)[2]), "=r"((r)[3]) \
                 : "r"(addr))
#define CP_ASYNC16(dst, src) \
    asm volatile("cp.async.cg.shared.global [%0], [%1], 16;" \
                 :: "r"(dst), "l"(src) : "memory")
#define CP_COMMIT() asm volatile("cp.async.commit_group;" ::: "memory")
#define CP_WAIT1()  asm volatile("cp.async.wait_group 1;" ::: "memory")

__device__ __forceinline__ void mma_f16(float* c, const uint32_t* a, const uint32_t* b) {
    asm volatile(
        "mma.sync.aligned.m16n8k16.row.col.f32.f16.f16.f32 "
        "{%0,%1,%2,%3}, {%4,%5,%6,%7}, {%8,%9}, {%0,%1,%2,%3};"
        : "+f"(c[0]), "+f"(c[1]), "+f"(c[2]), "+f"(c[3])
        : "r"(a[0]), "r"(a[1]), "r"(a[2]), "r"(a[3]), "r"(b[0]), "r"(b[1]));
}

// ---------------------------------------------------------------------------
// Prep (single kernel, vectorized): weight convert + pair-0 bias reduction
// ---------------------------------------------------------------------------
__global__ void prep_all(const float* __restrict__ wt) {
    int idx = blockIdx.x * blockDim.x + threadIdx.x;       // over 55*64*32 float4s
    if (idx < NPAIRS * CH * (OD / 4)) {
        int p = idx / (CH * (OD / 4));
        int r = idx - p * CH * (OD / 4);
        int c = r / (OD / 4);
        int o4 = (r - c * (OD / 4)) * 4;
        float4 w = *(const float4*)(wt + (size_t)(p * CH + c) * OD + o4);
        __half2 h0 = __floats2half2_rn(w.x, w.y);
        __half2 h1 = __floats2half2_rn(w.z, w.w);
        *(uint2*)&g_Bh[p][c * (BSTR / 2) + o4] =
            make_uint2(*(unsigned*)&h0, *(unsigned*)&h1);
    }
    if (blockIdx.x == 0 && threadIdx.x < OD) {
        int o = threadIdx.x;
        float s = 0.f;
        #pragma unroll
        for (int c = 0; c < CH; c++) s += wt[c * OD + o];   // pair 0 slice
        g_bias[o] = s;
    }
}

// ---------------------------------------------------------------------------
__global__ void __launch_bounds__(BDIM, 2)
qconv_pipe(const float* __restrict__ in, float* __restrict__ out) {
    extern __shared__ unsigned char smem[];
    const uint32_t sb = smem_to_u32(smem);
    int* mbase_s = (int*)(smem + MB_OFF);
    int* mmask_s = (int*)(smem + MK_OFF);

    const int tid  = threadIdx.x;
    const int wid  = tid >> 5;
    const int lane = tid & 31;
    const int gm0  = blockIdx.x * MT;

    if (tid < MT) {
        int gm  = gm0 + tid;
        int b   = gm / (HW * HW);
        int rem = gm - b * HW * HW;
        int h   = rem / HW;
        int w   = rem - h * HW;
        mbase_s[tid] = ((b * HW + (h - 1)) * HW + (w - 1)) * CH;
        int mask = 0;
        #pragma unroll
        for (int kk = 0; kk < 9; kk++) {
            int hh = h + kk / 3 - 1, ww = w + kk % 3 - 1;
            if (hh >= 0 && hh < HW && ww >= 0 && ww < HW) mask |= (1 << kk);
        }
        mmask_s[tid] = mask;
    }
    __syncthreads();

    // A-gen mapping: thread owns row am, 16-channel quarter cq
    const int am   = tid >> 2;
    const int cq   = (tid & 3) * 16;
    const int base = mbase_s[am];
    const int mask = mmask_s[am];

    // GEMM mapping: 8 warps = 2(M) x 4(N); warp tile 32 x 32
    const int m0 = (wid & 1) * 32;
    const int n0 = (wid >> 1) * 32;
    const uint32_t aoff = (uint32_t)((m0 + (lane & 15)) * ASTR + (lane >> 4) * 16);
    const uint32_t boff = (uint32_t)((lane & 15) * BSTR + (n0 + ((lane >> 4) & 1) * 8) * 2);

    float acc[2][4][4];
    #pragma unroll
    for (int mt = 0; mt < 2; mt++)
        #pragma unroll
        for (int nt = 0; nt < 4; nt++)
            #pragma unroll
            for (int q = 0; q < 4; q++) acc[mt][nt][q] = 0.f;

    const float4 ONES = make_float4(1.f, 1.f, 1.f, 1.f);
    const float4 ZERO = make_float4(0.f, 0.f, 0.f, 0.f);

    // ---- helpers ----
    auto issue_loads = [&](int p, float4* si4, float4* sj4) {
        const int i = cII[p], j = cJJ[p];
        const int kj = j - 1, ki = i - 1;
        const int offj = ((kj / 3) * HW + (kj % 3)) * CH;          // j >= 1 here
        const int offi = (i > 0) ? ((ki / 3) * HW + (ki % 3)) * CH : 0;
        const bool vj = (mask >> kj) & 1;
        const bool vi = (i == 0) || ((mask >> ki) & 1);
        #pragma unroll
        for (int g = 0; g < 4; g++) {
            const int c = cq + g * 4;
            sj4[g] = vj ? *(const float4*)(in + base + offj + c) : ZERO;
            si4[g] = (i == 0) ? ONES : (vi ? *(const float4*)(in + base + offi + c) : ZERO);
        }
    };
    auto store_A = [&](int buf, const float4* si4, const float4* sj4) {
        unsigned char* ah = smem + A_OFF(buf);
        #pragma unroll
        for (int g = 0; g < 4; g++) {
            const int c = cq + g * 4;
            __half2 hA = __floats2half2_rn(si4[g].x * sj4[g].x, si4[g].y * sj4[g].y);
            __half2 hB = __floats2half2_rn(si4[g].z * sj4[g].z, si4[g].w * sj4[g].w);
            *(uint2*)(ah + am * ASTR + c * 2) =
                make_uint2(*(unsigned*)&hA, *(unsigned*)&hB);
        }
    };
    auto stage_B = [&](int p, int buf) {
        const char* shp = (const char*)g_Bh[p];
        const uint32_t dh = sb + B_OFF(buf);
        #pragma unroll
        for (int t = 0; t < 5; t++) {
            int x = tid + t * BDIM;              // 1088 16B chunks
            if (x < BBUF_SZ / 16) CP_ASYNC16(dh + x * 16, shp + x * 16);
        }
    };

    // ---- prologue: pairs 1 and 2 ----
    stage_B(1, 0); CP_COMMIT();                  // group 0
    stage_B(2, 1); CP_COMMIT();                  // group 1
    {
        float4 si4[4], sj4[4];
        issue_loads(1, si4, sj4); store_A(0, si4, sj4);
        issue_loads(2, si4, sj4); store_A(1, si4, sj4);
    }

    // ---- main loop over GEMM pairs p = 1..54 ----
    int buf = 0, nxt = 2;
    for (int q = 0; q < NGEMM; q++) {
        const int p = q + 1;
        float4 si4[4], sj4[4];
        const bool more = (q + 2 < NGEMM);
        if (more) issue_loads(p + 2, si4, sj4);  // LDGs in flight across MMA

        CP_WAIT1();                              // B(p) landed (this thread)
        __syncthreads();                         // B(p)/A(p) visible; bufs free

        if (more) stage_B(p + 2, nxt);           // all warps past MMA(p-1)
        CP_COMMIT();                             // unconditional: group invariant

        // ---- MMA(p): 32 HMMA per warp, 2(M) x 4(N) fragments ----
        const uint32_t abase = sb + A_OFF(buf) + aoff;
        const uint32_t bbase = sb + B_OFF(buf) + boff;
        #pragma unroll
        for (int kk = 0; kk < 4; kk++) {
            uint32_t a0[4], a1[4];
            LDSM_X4(a0, abase + kk * 32);
            LDSM_X4(a1, abase + kk * 32 + 16 * ASTR);
            const uint32_t bb = bbase + kk * 16 * BSTR;
            #pragma unroll
            for (int t = 0; t < 4; t += 2) {
                uint32_t bh[4];
                LDSM_X4T(bh, bb + t * 16);
                mma_f16(acc[0][t],     a0, bh);
                mma_f16(acc[0][t + 1], a0, bh + 2);
                mma_f16(acc[1][t],     a1, bh);
                mma_f16(acc[1][t + 1], a1, bh + 2);
            }
        }

        if (more) store_A(nxt, si4, sj4);        // regs -> SMEM after MMA

        buf = (buf == 2) ? 0 : buf + 1;
        nxt = (nxt == 2) ? 0 : nxt + 1;
    }

    // ---- epilogue: add fp32 bias (pair 0) and store ----
    float* op = out + (size_t)gm0 * OD;
    const int rr = lane >> 2;
    const int cc = (lane & 3) * 2;
    #pragma unroll
    for (int mt = 0; mt < 2; mt++) {
        #pragma unroll
        for (int nt = 0; nt < 4; nt++) {
            const int r0 = m0 + mt * 16 + rr;
            const int cn = n0 + nt * 8 + cc;
            const float b0 = g_bias[cn], b1 = g_bias[cn + 1];
            *(float2*)(op + (size_t)r0 * OD + cn) =
                make_float2(acc[mt][nt][0] + b0, acc[mt][nt][1] + b1);
            *(float2*)(op + (size_t)(r0 + 8) * OD + cn) =
                make_float2(acc[mt][nt][2] + b0, acc[mt][nt][3] + b1);
        }
    }
}

// ---------------------------------------------------------------------------
extern "C" void kernel_launch(void* const* d_in, const int* in_sizes, int n_in,
                              void* d_out, int out_size) {
    const float* in = (const float*)d_in[0];
    const float* wt = (const float*)d_in[1];
    if (n_in >= 2 && in_sizes[0] == NPAIRS * CH * OD) {
        const float* t = in; in = wt; wt = t;
    }
    float* out = (float*)d_out;

    prep_all<<<(NPAIRS * CH * (OD / 4) + 255) / 256, 256>>>(wt);

    cudaFuncSetAttribute(qconv_pipe,
                         cudaFuncAttributeMaxDynamicSharedMemorySize, SMEM_TOTAL);
    qconv_pipe<<<NTILES, BDIM, SMEM_TOTAL>>>(in, out);
}

// round 15
// speedup vs baseline: 1.1904x; 1.0224x over previous
#include <cuda_runtime.h>
#include <cuda_fp16.h>
#include <cstdint>

// ============================================================================
// QuadraticConv2D via fp16 HMMA GEMM, register-carried pipeline (depth 3).
//   - 2M x 4N warp grid, triple-buffered SMEM, wait_group 1
//   - p=0 folded into fp32 bias; merged vectorized prep kernel
//   - main loop fully unrolled in buffer-period triples (54 = 18 x 3):
//     buf/nxt are compile-time -> SMEM addresses fold to immediates
// out[m,o] = bias[o] + sum_{p=(i,j)>0} sum_c S_i[m,c]*S_j[m,c]*W[p,c,o]
// ============================================================================

#define HW     56
#define CH     64
#define OD     128
#define NPOS   (8 * 56 * 56)      // 25088
#define MT     64                 // M rows per CTA
#define NTILES (NPOS / MT)        // 392
#define BDIM   256
#define NPAIRS 55
#define NGEMM  54                 // pairs 1..54 go through the GEMM

#define ASTR   144                // A row stride bytes
#define BSTR   272                // B row stride bytes

// SMEM layout (bytes), triple buffered
#define ABUF_SZ   9216            // 64 x 144
#define A_OFF(b)  ((b) * ABUF_SZ)                 // b in 0..2
#define BBUF_SZ   17408           // 64 x 272
#define B_OFF(b)  (27648 + (b) * BBUF_SZ)
#define MB_OFF    79872
#define MK_OFF    80128
#define SMEM_TOTAL 80384

// pre-converted weights [p][c*136 + o] fp16, and fp32 bias from pair 0
__device__ __align__(16) __half g_Bh[NPAIRS][CH * (BSTR / 2)];
__device__ __align__(16) float  g_bias[OD];

__constant__ unsigned char cII[55] = {
    0,0,0,0,0,0,0,0,0,0, 1,1,1,1,1,1,1,1,1, 2,2,2,2,2,2,2,2,
    3,3,3,3,3,3,3, 4,4,4,4,4,4, 5,5,5,5,5, 6,6,6,6, 7,7,7, 8,8, 9};
__constant__ unsigned char cJJ[55] = {
    0,1,2,3,4,5,6,7,8,9, 1,2,3,4,5,6,7,8,9, 2,3,4,5,6,7,8,9,
    3,4,5,6,7,8,9, 4,5,6,7,8,9, 5,6,7,8,9, 6,7,8,9, 7,8,9, 8,9, 9};

__device__ __forceinline__ uint32_t smem_to_u32(const void* p) {
    uint32_t a;
    asm("{ .reg .u64 t; cvta.to.shared.u64 t, %1; cvt.u32.u64 %0, t; }"
        : "=r"(a) : "l"(p));
    return a;
}

#define LDSM_X4(r, addr) \
    asm volatile("ldmatrix.sync.aligned.m8n8.x4.shared.b16 {%0,%1,%2,%3}, [%4];" \
                 : "=r"((r)[0]), "=r"((r)[1]), "=r"((r)[2]), "=r"((r)[3]) \
                 : "r"(addr))
#define LDSM_X4T(r, addr) \
    asm volatile("ldmatrix.sync.aligned.m8n8.x4.trans.shared.b16 {%0,%1,%2,%3}, [%4];" \
                 : "=r"((r)[0]), "=r"((r)[1]), "=r"((r)[2]), "=r"((r)[3]) \
                 : "r"(addr))
#define CP_ASYNC16(dst, src) \
    asm volatile("cp.async.cg.shared.global [%0], [%1], 16;" \
                 :: "r"(dst), "l"(src) : "memory")
#define CP_COMMIT() asm volatile("cp.async.commit_group;" ::: "memory")
#define CP_WAIT1()  asm volatile("cp.async.wait_group 1;" ::: "memory")

__device__ __forceinline__ void mma_f16(float* c, const uint32_t* a, const uint32_t* b) {
    asm volatile(
        "mma.sync.aligned.m16n8k16.row.col.f32.f16.f16.f32 "
        "{%0,%1,%2,%3}, {%4,%5,%6,%7}, {%8,%9}, {%0,%1,%2,%3};"
        : "+f"(c[0]), "+f"(c[1]), "+f"(c[2]), "+f"(c[3])
        : "r"(a[0]), "r"(a[1]), "r"(a[2]), "r"(a[3]), "r"(b[0]), "r"(b[1]));
}

// ---------------------------------------------------------------------------
// Prep (single kernel, vectorized): weight convert + pair-0 bias reduction
// ---------------------------------------------------------------------------
__global__ void prep_all(const float* __restrict__ wt) {
    int idx = blockIdx.x * blockDim.x + threadIdx.x;       // over 55*64*32 float4s
    if (idx < NPAIRS * CH * (OD / 4)) {
        int p = idx / (CH * (OD / 4));
        int r = idx - p * (CH * (OD / 4));
        int c = r / (OD / 4);
        int o4 = (r - c * (OD / 4)) * 4;
        float4 w = *(const float4*)(wt + (size_t)(p * CH + c) * OD + o4);
        __half2 h0 = __floats2half2_rn(w.x, w.y);
        __half2 h1 = __floats2half2_rn(w.z, w.w);
        *(uint2*)&g_Bh[p][c * (BSTR / 2) + o4] =
            make_uint2(*(unsigned*)&h0, *(unsigned*)&h1);
    }
    if (blockIdx.x == 0 && threadIdx.x < OD) {
        int o = threadIdx.x;
        float s = 0.f;
        #pragma unroll
        for (int c = 0; c < CH; c++) s += wt[c * OD + o];   // pair 0 slice
        g_bias[o] = s;
    }
}

// ---------------------------------------------------------------------------
__global__ void __launch_bounds__(BDIM, 2)
qconv_pipe(const float* __restrict__ in, float* __restrict__ out) {
    extern __shared__ unsigned char smem[];
    const uint32_t sb = smem_to_u32(smem);
    int* mbase_s = (int*)(smem + MB_OFF);
    int* mmask_s = (int*)(smem + MK_OFF);

    const int tid  = threadIdx.x;
    const int wid  = tid >> 5;
    const int lane = tid & 31;
    const int gm0  = blockIdx.x * MT;

    if (tid < MT) {
        int gm  = gm0 + tid;
        int b   = gm / (HW * HW);
        int rem = gm - b * HW * HW;
        int h   = rem / HW;
        int w   = rem - h * HW;
        mbase_s[tid] = ((b * HW + (h - 1)) * HW + (w - 1)) * CH;
        int mask = 0;
        #pragma unroll
        for (int kk = 0; kk < 9; kk++) {
            int hh = h + kk / 3 - 1, ww = w + kk % 3 - 1;
            if (hh >= 0 && hh < HW && ww >= 0 && ww < HW) mask |= (1 << kk);
        }
        mmask_s[tid] = mask;
    }
    __syncthreads();

    // A-gen mapping: thread owns row am, 16-channel quarter cq
    const int am   = tid >> 2;
    const int cq   = (tid & 3) * 16;
    const int base = mbase_s[am];
    const int mask = mmask_s[am];

    // GEMM mapping: 8 warps = 2(M) x 4(N); warp tile 32 x 32
    const int m0 = (wid & 1) * 32;
    const int n0 = (wid >> 1) * 32;
    const uint32_t aoff = (uint32_t)((m0 + (lane & 15)) * ASTR + (lane >> 4) * 16);
    const uint32_t boff = (uint32_t)((lane & 15) * BSTR + (n0 + ((lane >> 4) & 1) * 8) * 2);

    float acc[2][4][4];
    #pragma unroll
    for (int mt = 0; mt < 2; mt++)
        #pragma unroll
        for (int nt = 0; nt < 4; nt++)
            #pragma unroll
            for (int q = 0; q < 4; q++) acc[mt][nt][q] = 0.f;

    const float4 ONES = make_float4(1.f, 1.f, 1.f, 1.f);
    const float4 ZERO = make_float4(0.f, 0.f, 0.f, 0.f);

    // ---- helpers ----
    auto issue_loads = [&](int p, float4* si4, float4* sj4) {
        const int i = cII[p], j = cJJ[p];
        const int kj = j - 1, ki = i - 1;
        const int offj = ((kj / 3) * HW + (kj % 3)) * CH;          // j >= 1 here
        const int offi = (i > 0) ? ((ki / 3) * HW + (ki % 3)) * CH : 0;
        const bool vj = (mask >> kj) & 1;
        const bool vi = (i == 0) || ((mask >> ki) & 1);
        #pragma unroll
        for (int g = 0; g < 4; g++) {
            const int c = cq + g * 4;
            sj4[g] = vj ? *(const float4*)(in + base + offj + c) : ZERO;
            si4[g] = (i == 0) ? ONES : (vi ? *(const float4*)(in + base + offi + c) : ZERO);
        }
    };
    auto store_A = [&](uint32_t a_off_bytes, const float4* si4, const float4* sj4) {
        unsigned char* ah = smem + a_off_bytes;
        #pragma unroll
        for (int g = 0; g < 4; g++) {
            const int c = cq + g * 4;
            __half2 hA = __floats2half2_rn(si4[g].x * sj4[g].x, si4[g].y * sj4[g].y);
            __half2 hB = __floats2half2_rn(si4[g].z * sj4[g].z, si4[g].w * sj4[g].w);
            *(uint2*)(ah + am * ASTR + c * 2) =
                make_uint2(*(unsigned*)&hA, *(unsigned*)&hB);
        }
    };
    auto stage_B = [&](int p, uint32_t b_off_bytes) {
        const char* shp = (const char*)g_Bh[p];
        const uint32_t dh = sb + b_off_bytes;
        // 1088 16B chunks = 4*256 + 64
        #pragma unroll
        for (int t = 0; t < 4; t++) {
            const int x = tid + t * BDIM;
            CP_ASYNC16(dh + x * 16, shp + x * 16);
        }
        if (tid < 64) {
            const int x = 1024 + tid;
            CP_ASYNC16(dh + x * 16, shp + x * 16);
        }
    };
    auto mma_pair = [&](uint32_t a_off_bytes, uint32_t b_off_bytes) {
        const uint32_t abase = sb + a_off_bytes + aoff;
        const uint32_t bbase = sb + b_off_bytes + boff;
        #pragma unroll
        for (int kk = 0; kk < 4; kk++) {
            uint32_t a0[4], a1[4];
            LDSM_X4(a0, abase + kk * 32);
            LDSM_X4(a1, abase + kk * 32 + 16 * ASTR);
            const uint32_t bb = bbase + kk * 16 * BSTR;
            #pragma unroll
            for (int t = 0; t < 4; t += 2) {
                uint32_t bh[4];
                LDSM_X4T(bh, bb + t * 16);
                mma_f16(acc[0][t],     a0, bh);
                mma_f16(acc[0][t + 1], a0, bh + 2);
                mma_f16(acc[1][t],     a1, bh);
                mma_f16(acc[1][t + 1], a1, bh + 2);
            }
        }
    };

    // One pipeline step; BUF/NXT are compile-time constants at each call site.
    #define STEP(BUF, NXT, PP, MORE) do {                                      \
        float4 si4[4], sj4[4];                                                 \
        if (MORE) issue_loads((PP) + 2, si4, sj4);  /* LDGs fly across MMA */  \
        CP_WAIT1();                    /* B(PP) landed (this thread) */        \
        __syncthreads();               /* B/A(PP) visible; bufs free */        \
        if (MORE) stage_B((PP) + 2, B_OFF(NXT));                               \
        CP_COMMIT();                   /* unconditional: group invariant */    \
        mma_pair(A_OFF(BUF), B_OFF(BUF));           /* 32 HMMA per warp */     \
        if (MORE) store_A(A_OFF(NXT), si4, sj4);    /* regs -> SMEM */         \
    } while (0)

    // ---- prologue: pairs 1 and 2 ----
    stage_B(1, B_OFF(0)); CP_COMMIT();           // group 0
    stage_B(2, B_OFF(1)); CP_COMMIT();           // group 1
    {
        float4 si4[4], sj4[4];
        issue_loads(1, si4, sj4); store_A(A_OFF(0), si4, sj4);
        issue_loads(2, si4, sj4); store_A(A_OFF(1), si4, sj4);
    }

    // ---- main loop: 17 full triples (q = 0..50), buf pattern 0,1,2 ----
    int p = 1;
    #pragma unroll 1
    for (int t3 = 0; t3 < 17; t3++) {
        STEP(0, 2, p,     true);
        STEP(1, 0, p + 1, true);
        STEP(2, 1, p + 2, true);
        p += 3;
    }
    // ---- tail triple: q = 51, 52, 53 (p = 52, 53, 54) ----
    STEP(0, 2, p,     true);    // stages pair 54
    STEP(1, 0, p + 1, false);
    STEP(2, 1, p + 2, false);
    #undef STEP

    // ---- epilogue: add fp32 bias (pair 0) and store ----
    float* op = out + (size_t)gm0 * OD;
    const int rr = lane >> 2;
    const int cc = (lane & 3) * 2;
    #pragma unroll
    for (int mt = 0; mt < 2; mt++) {
        #pragma unroll
        for (int nt = 0; nt < 4; nt++) {
            const int r0 = m0 + mt * 16 + rr;
            const int cn = n0 + nt * 8 + cc;
            const float b0 = g_bias[cn], b1 = g_bias[cn + 1];
            *(float2*)(op + (size_t)r0 * OD + cn) =
                make_float2(acc[mt][nt][0] + b0, acc[mt][nt][1] + b1);
            *(float2*)(op + (size_t)(r0 + 8) * OD + cn) =
                make_float2(acc[mt][nt][2] + b0, acc[mt][nt][3] + b1);
        }
    }
}

// ---------------------------------------------------------------------------
extern "C" void kernel_launch(void* const* d_in, const int* in_sizes, int n_in,
                              void* d_out, int out_size) {
    const float* in = (const float*)d_in[0];
    const float* wt = (const float*)d_in[1];
    if (n_in >= 2 && in_sizes[0] == NPAIRS * CH * OD) {
        const float* t = in; in = wt; wt = t;
    }
    float* out = (float*)d_out;

    prep_all<<<(NPAIRS * CH * (OD / 4) + 255) / 256, 256>>>(wt);

    cudaFuncSetAttribute(qconv_pipe,
                         cudaFuncAttributeMaxDynamicSharedMemorySize, SMEM_TOTAL);
    qconv_pipe<<<NTILES, BDIM, SMEM_TOTAL>>>(in, out);
}